// round 4
// baseline (speedup 1.0000x reference)
#include <cuda_runtime.h>
#include <math.h>

#define BB 32
#define VV 518
#define SS 2048
#define BV (BB*VV)          // 16576 rows
#define NTOK (BB*SS)        // 65536 (b,s) positions
#define NW 16               // v-chunks (warps) in k_cols
#define TS 128              // s-positions per k_cols block
#define NBLK_COLS (BB*(SS/TS))    // 512
#define VCHUNK ((VV + NW - 1)/NW) // 33
#define ROWBYTES (SS*4)           // 8192

// Persistent scratch (allocations forbidden). Invariant: g_sum_*, g_done are
// zero between kernel_launch calls (reset by the completing block of k_cols).
__device__ double g_sum_nll = 0.0;
__device__ double g_sum_mask = 0.0;
__device__ unsigned int g_done = 0;
__device__ float  g_c[BV];       // log-sum-exp over S per (b,v)
__device__ int    g_t64;         // 1 if target buffer is int64

// ---------------------------------------------------------------------------
// Pass A: c[b,v] = log(sum_s exp(x)). One warp per row, float4 streaming.
// No max-tracking: inputs are N(0,1), sum_s exp(x) < 1e5, safely in fp32.
// Block 0 also detects target dtype (odd 32-bit words all zero over 64
// entries <=> little-endian int64 with values < 518).
// ---------------------------------------------------------------------------
__global__ void k_rows(const float* __restrict__ X, const int* __restrict__ t32) {
    if (blockIdx.x == 0) {
        __shared__ int nz;
        if (threadIdx.x == 0) nz = 0;
        __syncthreads();
        if (threadIdx.x < 64 && t32[threadIdx.x * 2 + 1] != 0) atomicOr(&nz, 1);
        __syncthreads();
        if (threadIdx.x == 0) g_t64 = nz ? 0 : 1;
    }

    int warp = (blockIdx.x * blockDim.x + threadIdx.x) >> 5;
    int lane = threadIdx.x & 31;
    if (warp >= BV) return;
    const float4* row = (const float4*)(X + (size_t)warp * SS);

    float a0 = 0.f, a1 = 0.f, a2 = 0.f, a3 = 0.f;
#pragma unroll 4
    for (int i = lane; i < SS/4; i += 32) {
        float4 v = row[i];
        a0 += __expf(v.x); a1 += __expf(v.y);
        a2 += __expf(v.z); a3 += __expf(v.w);
    }
    float a = (a0 + a1) + (a2 + a3);
#pragma unroll
    for (int o = 16; o; o >>= 1) a += __shfl_xor_sync(0xffffffffu, a, o);
    if (lane == 0) g_c[warp] = __logf(a);
}

// ---------------------------------------------------------------------------
// Pass B: block = (b, 128 s-positions), 512 threads. 16 warps each own a
// 33-wide V-chunk; every thread owns 4 consecutive columns (float4 loads,
// 512B/warp/row). Per column: sum_v exp(x) (NLL) and argmax_v (x - c[v])
// (pred). x[target] is gathered directly in the combine phase (no per-element
// check). Shared-memory combine across chunks (ascending order keeps
// jnp.argmax first-max tie-breaking), then mask + block reduction.
// The last block to finish writes the scalar result and resets accumulators.
// ---------------------------------------------------------------------------
__global__ __launch_bounds__(NW*32, 3)
void k_cols(const float* __restrict__ X, const void* __restrict__ tptr,
            float* __restrict__ out) {
    __shared__ float sc[VV];
    __shared__ float s_sum[NW][TS];
    __shared__ float s_best[NW][TS];
    __shared__ int   s_bv[NW][TS];
    __shared__ double s_red[8];     // 4 nll partials + 4 mask partials

    const int b  = blockIdx.x >> 4;
    const int s0 = (blockIdx.x & 15) * TS;
    const int tid = threadIdx.x, w = tid >> 5, lane = tid & 31;

    for (int i = tid; i < VV; i += blockDim.x) sc[i] = g_c[b * VV + i];
    __syncthreads();

    const int vlo = w * VCHUNK;
    const int vhi = min(VV, vlo + VCHUNK);

    float sum[4]  = {0.f, 0.f, 0.f, 0.f};
    float best[4] = {-INFINITY, -INFINITY, -INFINITY, -INFINITY};
    int   bv[4]   = {0, 0, 0, 0};

    const char* p = (const char*)(X + (size_t)b * VV * SS + s0)
                  + (size_t)lane * 16 + (size_t)vlo * ROWBYTES;
#pragma unroll 3
    for (int v = vlo; v < vhi; v++, p += ROWBYTES) {
        float4 x = *(const float4*)p;
        float c = sc[v];
        float xv[4] = {x.x, x.y, x.z, x.w};
#pragma unroll
        for (int k = 0; k < 4; k++) {
            sum[k] += __expf(xv[k]);
            float score = xv[k] - c;
            if (score > best[k]) { best[k] = score; bv[k] = v; }
        }
    }
#pragma unroll
    for (int k = 0; k < 4; k++) {
        int j = lane * 4 + k;
        s_sum[w][j]  = sum[k];
        s_best[w][j] = best[k];
        s_bv[w][j]   = bv[k];
    }
    __syncthreads();

    double nll_d = 0.0, mask_d = 0.0;
    if (tid < TS) {
        const int j = tid;

        // target + direct gather of x[b, tgt, s] (one scattered LDG per token)
        int tgt;
        {
            int idx = b * SS + s0 + j;
            if (g_t64) tgt = (int)((const long long*)tptr)[idx];
            else       tgt = ((const int*)tptr)[idx];
        }
        float txt = X[(size_t)b * VV * SS + (size_t)tgt * SS + s0 + j];

        float tsum = 0.f, tbest = -INFINITY;
        int tbv = 0;
#pragma unroll
        for (int c = 0; c < NW; c++) {            // ascending order = first-max ties
            tsum += s_sum[c][j];
            if (s_best[c][j] > tbest) { tbest = s_best[c][j]; tbv = s_bv[c][j]; }
        }
        float nll = __logf(tsum) - txt;

        int pt = (tbv < 128) ? 0 : (tbv < 289) ? 1 : (tbv < 390) ? 2 : 3;
        int tt = (tgt < 128) ? 0 : (tgt < 289) ? 1 : (tgt < 390) ? 2 : 3;
        float mask;
        if (pt != tt) {
            mask = 1.0f;
        } else if (pt == 0) {
            mask = 0.5f;
        } else {
            float denom = (pt == 1) ? 160.f : (pt == 2) ? 100.f : 128.f;
            float diff = fabsf((float)(tbv - tgt));
            mask = 0.5f * diff / denom;
        }
        nll_d  = (double)nll;
        mask_d = (double)mask;
    }
    if (tid < TS) {
#pragma unroll
        for (int o = 16; o; o >>= 1) {
            nll_d  += __shfl_xor_sync(0xffffffffu, nll_d, o);
            mask_d += __shfl_xor_sync(0xffffffffu, mask_d, o);
        }
        if (lane == 0) { s_red[w] = nll_d; s_red[4 + w] = mask_d; }
    }
    __syncthreads();
    if (tid == 0) {
        double n = s_red[0] + s_red[1] + s_red[2] + s_red[3];
        double m = s_red[4] + s_red[5] + s_red[6] + s_red[7];
        atomicAdd(&g_sum_nll, n);
        atomicAdd(&g_sum_mask, m);
        __threadfence();
        unsigned int done = atomicAdd(&g_done, 1u);
        if (done == NBLK_COLS - 1) {
            double nm = g_sum_nll / (double)NTOK;
            double mm = g_sum_mask / (double)NTOK;
            out[0] = (float)(nm * (1.0 + mm));
            g_sum_nll = 0.0;
            g_sum_mask = 0.0;
            g_done = 0u;
        }
    }
}

extern "C" void kernel_launch(void* const* d_in, const int* in_sizes, int n_in,
                              void* d_out, int out_size) {
    const float* X   = (const float*)d_in[0];
    const void*  tgt = d_in[1];
    float* out = (float*)d_out;

    k_rows<<<BV / 8, 256>>>(X, (const int*)tgt);   // 2072 blocks, 1 warp/row
    k_cols<<<NBLK_COLS, NW * 32>>>(X, tgt, out);   // 512 blocks x 512 threads
}

// round 5
// speedup vs baseline: 1.0371x; 1.0371x over previous
#include <cuda_runtime.h>
#include <math.h>

#define BB 32
#define VV 518
#define SS 2048
#define BV (BB*VV)          // 16576 rows
#define NTOK (BB*SS)        // 65536 (b,s) positions
#define NW 16               // v-chunks (warps) in k_cols
#define TS 128              // s-positions per tile
#define NTILE (BB*(SS/TS))  // 512 tiles
#define NBLK 296            // 2 per SM, single wave
#define ROWBYTES (SS*4)     // 8192

// Persistent scratch (allocations forbidden). g_sum_*, g_done are zero
// between kernel_launch calls (reset by the completing block of k_cols);
// g_tile is reset by k_rows each call (stream-ordered before k_cols).
__device__ double g_sum_nll = 0.0;
__device__ double g_sum_mask = 0.0;
__device__ unsigned int g_done = 0;
__device__ unsigned int g_tile = 0;
__device__ float  g_c[BV];       // log-sum-exp over S per (b,v)
__device__ int    g_t64;         // 1 if target buffer is int64

// ---------------------------------------------------------------------------
// Pass A: c[b,v] = log(sum_s exp(x)). One warp per row, float4 streaming.
// No max-tracking: inputs are N(0,1), sum_s exp(x) < 1e5, safely in fp32.
// Block 0 also detects target dtype and resets the tile counter.
// ---------------------------------------------------------------------------
__global__ void k_rows(const float* __restrict__ X, const int* __restrict__ t32) {
    if (blockIdx.x == 0) {
        __shared__ int nz;
        if (threadIdx.x == 0) { nz = 0; g_tile = 0u; }
        __syncthreads();
        if (threadIdx.x < 64 && t32[threadIdx.x * 2 + 1] != 0) atomicOr(&nz, 1);
        __syncthreads();
        if (threadIdx.x == 0) g_t64 = nz ? 0 : 1;
    }

    int warp = (blockIdx.x * blockDim.x + threadIdx.x) >> 5;
    int lane = threadIdx.x & 31;
    if (warp >= BV) return;
    const float4* row = (const float4*)(X + (size_t)warp * SS);

    float a0 = 0.f, a1 = 0.f, a2 = 0.f, a3 = 0.f;
#pragma unroll 4
    for (int i = lane; i < SS/4; i += 32) {
        float4 v = row[i];
        a0 += __expf(v.x); a1 += __expf(v.y);
        a2 += __expf(v.z); a3 += __expf(v.w);
    }
    float a = (a0 + a1) + (a2 + a3);
#pragma unroll
    for (int o = 16; o; o >>= 1) a += __shfl_xor_sync(0xffffffffu, a, o);
    if (lane == 0) g_c[warp] = __logf(a);
}

// per-element update: sum of exp, argmax of (x - c) with first-max ties
#define ACC(X4, C, V)                                              \
    do {                                                           \
        float _xv[4] = {(X4).x, (X4).y, (X4).z, (X4).w};           \
        _Pragma("unroll")                                          \
        for (int _k = 0; _k < 4; _k++) {                           \
            sum[_k] += __expf(_xv[_k]);                            \
            float _sc = _xv[_k] - (C);                             \
            if (_sc > best[_k]) { best[_k] = _sc; bv[_k] = (V); }  \
        }                                                          \
    } while (0)

// ---------------------------------------------------------------------------
// Pass B: persistent-ish blocks (296 = 2/SM) pull (b, s-chunk) tiles from an
// atomic counter. 16 warps split V (first 6 warps: 33 rows, rest: 32); each
// thread owns 4 consecutive s-columns (float4). The inner loop front-batches
// 4 independent LDG.128 per iteration for MLP. x[target] is gathered directly
// in the combine phase. Last tile finisher writes the scalar + resets.
// ---------------------------------------------------------------------------
__global__ __launch_bounds__(NW*32, 2)
void k_cols(const float* __restrict__ X, const void* __restrict__ tptr,
            float* __restrict__ out) {
    __shared__ float sc[VV];
    __shared__ float s_sum[NW][TS];
    __shared__ float s_best[NW][TS];
    __shared__ int   s_bv[NW][TS];
    __shared__ double s_red[8];
    __shared__ unsigned int s_tile;

    const int tid = threadIdx.x, w = tid >> 5, lane = tid & 31;
    // warp v-range: warps 0..5 get 33 rows, 6..15 get 32  (6*33+10*32 = 518)
    const int vlo = w * 32 + min(w, 6);
    const int vhi = vlo + ((w < 6) ? 33 : 32);

    for (;;) {
        if (tid == 0) s_tile = atomicAdd(&g_tile, 1u);
        __syncthreads();
        const unsigned int t = s_tile;
        if (t >= NTILE) break;

        const int b  = t >> 4;
        const int s0 = (t & 15) * TS;

        for (int i = tid; i < VV; i += NW*32) sc[i] = g_c[b * VV + i];
        __syncthreads();

        float sum[4]  = {0.f, 0.f, 0.f, 0.f};
        float best[4] = {-INFINITY, -INFINITY, -INFINITY, -INFINITY};
        int   bv[4]   = {0, 0, 0, 0};

        const char* p = (const char*)(X + (size_t)b * VV * SS + s0)
                      + (size_t)lane * 16 + (size_t)vlo * ROWBYTES;
        int v = vlo;
        for (; v + 4 <= vhi; v += 4, p += 4*ROWBYTES) {
            // 4 independent 128-bit loads issued before any dependent compute
            float4 x0 = *(const float4*)(p);
            float4 x1 = *(const float4*)(p + ROWBYTES);
            float4 x2 = *(const float4*)(p + 2*ROWBYTES);
            float4 x3 = *(const float4*)(p + 3*ROWBYTES);
            float c0 = sc[v], c1 = sc[v+1], c2 = sc[v+2], c3 = sc[v+3];
            ACC(x0, c0, v);
            ACC(x1, c1, v+1);
            ACC(x2, c2, v+2);
            ACC(x3, c3, v+3);
        }
        for (; v < vhi; v++, p += ROWBYTES) {
            float4 x0 = *(const float4*)(p);
            float c0 = sc[v];
            ACC(x0, c0, v);
        }

#pragma unroll
        for (int k = 0; k < 4; k++) {
            int j = lane * 4 + k;
            s_sum[w][j]  = sum[k];
            s_best[w][j] = best[k];
            s_bv[w][j]   = bv[k];
        }
        __syncthreads();

        double nll_d = 0.0, mask_d = 0.0;
        if (tid < TS) {
            const int j = tid;
            int tgt;
            {
                int idx = b * SS + s0 + j;
                if (g_t64) tgt = (int)((const long long*)tptr)[idx];
                else       tgt = ((const int*)tptr)[idx];
            }
            float txt = X[(size_t)b * VV * SS + (size_t)tgt * SS + s0 + j];

            float tsum = 0.f, tbest = -INFINITY;
            int tbv = 0;
#pragma unroll
            for (int c = 0; c < NW; c++) {        // ascending = first-max ties
                tsum += s_sum[c][j];
                if (s_best[c][j] > tbest) { tbest = s_best[c][j]; tbv = s_bv[c][j]; }
            }
            float nll = __logf(tsum) - txt;

            int pt = (tbv < 128) ? 0 : (tbv < 289) ? 1 : (tbv < 390) ? 2 : 3;
            int tt = (tgt < 128) ? 0 : (tgt < 289) ? 1 : (tgt < 390) ? 2 : 3;
            float mask;
            if (pt != tt) {
                mask = 1.0f;
            } else if (pt == 0) {
                mask = 0.5f;
            } else {
                float denom = (pt == 1) ? 160.f : (pt == 2) ? 100.f : 128.f;
                mask = 0.5f * fabsf((float)(tbv - tgt)) / denom;
            }
            nll_d  = (double)nll;
            mask_d = (double)mask;

#pragma unroll
            for (int o = 16; o; o >>= 1) {
                nll_d  += __shfl_xor_sync(0xffffffffu, nll_d, o);
                mask_d += __shfl_xor_sync(0xffffffffu, mask_d, o);
            }
            if (lane == 0) { s_red[w] = nll_d; s_red[4 + w] = mask_d; }
        }
        __syncthreads();
        if (tid == 0) {
            double n = s_red[0] + s_red[1] + s_red[2] + s_red[3];
            double m = s_red[4] + s_red[5] + s_red[6] + s_red[7];
            atomicAdd(&g_sum_nll, n);
            atomicAdd(&g_sum_mask, m);
            __threadfence();
            unsigned int done = atomicAdd(&g_done, 1u);
            if (done == NTILE - 1) {
                double nm = g_sum_nll / (double)NTOK;
                double mm = g_sum_mask / (double)NTOK;
                out[0] = (float)(nm * (1.0 + mm));
                g_sum_nll = 0.0;
                g_sum_mask = 0.0;
                g_done = 0u;
            }
        }
        __syncthreads();   // protect smem reuse across tile iterations
    }
}

extern "C" void kernel_launch(void* const* d_in, const int* in_sizes, int n_in,
                              void* d_out, int out_size) {
    const float* X   = (const float*)d_in[0];
    const void*  tgt = d_in[1];
    float* out = (float*)d_out;

    k_rows<<<BV / 8, 256>>>(X, (const int*)tgt);   // 2072 blocks, 1 warp/row
    k_cols<<<NBLK, NW * 32>>>(X, tgt, out);        // 296 blocks, dynamic tiles
}